// round 10
// baseline (speedup 1.0000x reference)
#include <cuda_runtime.h>

#define B_  4
#define C_  64
#define N_  4096
#define CK  32       // f/g channel count
#define MT  64       // rows (query pixels) per CTA
#define NT  64       // key tile width

// Scratch for projected tensors (bss, no allocation)
__device__ float g_fbuf[B_ * CK * N_];
__device__ float g_gbuf[B_ * CK * N_];
__device__ float g_hbuf[B_ * C_ * N_];

// ---------------------------------------------------------------------------
// Projection: out[b, oc0+o, n] = sum_c W[oc0+o, c] * in[b, c, n] + bias[oc0+o]
// grid.x covers B*N / 256 pixels, grid.y covers output channels in chunks of 16
// ---------------------------------------------------------------------------
__global__ __launch_bounds__(256) void proj_kernel(
    const float* __restrict__ W, const float* __restrict__ bias,
    const float* __restrict__ in, float* __restrict__ out, int OC)
{
    __shared__ float Ws[16][64];
    const int oc0 = blockIdx.y * 16;
    const int t = threadIdx.x;
    for (int i = t; i < 16 * 64; i += 256)
        Ws[i >> 6][i & 63] = W[(oc0 + (i >> 6)) * C_ + (i & 63)];
    __syncthreads();

    const int pix = blockIdx.x * 256 + t;        // 0 .. B*N-1
    const int b = pix >> 12;                      // / 4096
    const int n = pix & (N_ - 1);
    const float* inp = in + (size_t)b * C_ * N_ + n;

    float acc[16];
#pragma unroll
    for (int o = 0; o < 16; o++) acc[o] = bias[oc0 + o];

#pragma unroll 4
    for (int c = 0; c < C_; c++) {
        float v = inp[(size_t)c * N_];
#pragma unroll
        for (int o = 0; o < 16; o++) acc[o] = fmaf(Ws[o][c], v, acc[o]);
    }

    float* op = out + (size_t)b * OC * N_ + (size_t)oc0 * N_ + n;
#pragma unroll
    for (int o = 0; o < 16; o++) op[(size_t)o * N_] = acc[o];
}

// ---------------------------------------------------------------------------
// Fused flash-attention: per CTA = (batch b, 64-row query block m0)
//   S[m,n] = sum_c g[c,m]*f[c,n];  beta = softmax_n(S);  O[m,c] = sum_n beta*h[c,n]
//   out[b,c,m] = gamma * O[m,c] + x[b,c,m]
// 256 threads, thread (ty,tx) owns 4x4 register tile: rows ty*4.., cols tx*4..
// ---------------------------------------------------------------------------
__global__ __launch_bounds__(256, 2) void attn_kernel(
    const float* __restrict__ x, const float* __restrict__ gamma_p,
    float* __restrict__ out)
{
    __shared__ float gT[MT][CK + 4];   // [m][c]
    __shared__ float fS[CK][NT + 4];   // [c][n]
    __shared__ float hS[C_][NT + 4];   // [c][n]
    __shared__ float pS[MT][NT + 4];   // [m][n]

    const int b  = blockIdx.y;
    const int m0 = blockIdx.x * MT;
    const int t  = threadIdx.x;
    const int ty = t >> 4, tx = t & 15;
    const int r0 = ty * 4;             // local row base (m)
    const int c0 = tx * 4;             // local col base (n in S, channel in O)

    const float* fb = g_fbuf + (size_t)b * CK * N_;
    const float* gb = g_gbuf + (size_t)b * CK * N_;
    const float* hb = g_hbuf + (size_t)b * C_ * N_;

    // load g^T block once: gT[m][c] = g[c][m0+m]
    for (int v = t; v < MT * CK; v += 256) {
        int m = v & (MT - 1), c = v >> 6;
        gT[m][c] = gb[(size_t)c * N_ + m0 + m];
    }

    float mi[4], li[4], acc[4][4];
#pragma unroll
    for (int i = 0; i < 4; i++) {
        mi[i] = -1e30f; li[i] = 0.f;
#pragma unroll
        for (int j = 0; j < 4; j++) acc[i][j] = 0.f;
    }

    for (int n0 = 0; n0 < N_; n0 += NT) {
        // ---- load f/h tiles (float4, coalesced) ----
        for (int v = t; v < CK * (NT / 4); v += 256) {      // 512 float4 / 256 thr
            int c = v >> 4, q = (v & 15) * 4;
            *(float4*)&fS[c][q] = *(const float4*)&fb[(size_t)c * N_ + n0 + q];
        }
        for (int v = t; v < C_ * (NT / 4); v += 256) {      // 1024 float4
            int c = v >> 4, q = (v & 15) * 4;
            *(float4*)&hS[c][q] = *(const float4*)&hb[(size_t)c * N_ + n0 + q];
        }
        __syncthreads();

        // ---- S = g^T f  (64x64 tile, K=32) ----
        float s[4][4];
#pragma unroll
        for (int i = 0; i < 4; i++)
#pragma unroll
            for (int j = 0; j < 4; j++) s[i][j] = 0.f;

#pragma unroll 4
        for (int c = 0; c < CK; c += 4) {
            float4 bq0 = *(const float4*)&fS[c + 0][c0];
            float4 bq1 = *(const float4*)&fS[c + 1][c0];
            float4 bq2 = *(const float4*)&fS[c + 2][c0];
            float4 bq3 = *(const float4*)&fS[c + 3][c0];
            float br0[4] = {bq0.x, bq0.y, bq0.z, bq0.w};
            float br1[4] = {bq1.x, bq1.y, bq1.z, bq1.w};
            float br2[4] = {bq2.x, bq2.y, bq2.z, bq2.w};
            float br3[4] = {bq3.x, bq3.y, bq3.z, bq3.w};
#pragma unroll
            for (int i = 0; i < 4; i++) {
                float4 aq = *(const float4*)&gT[r0 + i][c];
#pragma unroll
                for (int j = 0; j < 4; j++) {
                    s[i][j] = fmaf(aq.x, br0[j], s[i][j]);
                    s[i][j] = fmaf(aq.y, br1[j], s[i][j]);
                    s[i][j] = fmaf(aq.z, br2[j], s[i][j]);
                    s[i][j] = fmaf(aq.w, br3[j], s[i][j]);
                }
            }
        }

        // ---- online softmax ----
#pragma unroll
        for (int i = 0; i < 4; i++) {
            float mt = fmaxf(fmaxf(s[i][0], s[i][1]), fmaxf(s[i][2], s[i][3]));
#pragma unroll
            for (int k = 1; k < 16; k <<= 1)
                mt = fmaxf(mt, __shfl_xor_sync(0xffffffffu, mt, k));
            float mn = fmaxf(mi[i], mt);
            float sc = __expf(mi[i] - mn);
            mi[i] = mn;
            float p0 = __expf(s[i][0] - mn);
            float p1 = __expf(s[i][1] - mn);
            float p2 = __expf(s[i][2] - mn);
            float p3 = __expf(s[i][3] - mn);
            s[i][0] = p0; s[i][1] = p1; s[i][2] = p2; s[i][3] = p3;
            float ls = (p0 + p1) + (p2 + p3);
#pragma unroll
            for (int k = 1; k < 16; k <<= 1)
                ls += __shfl_xor_sync(0xffffffffu, ls, k);
            li[i] = li[i] * sc + ls;
#pragma unroll
            for (int j = 0; j < 4; j++) acc[i][j] *= sc;
        }

        // ---- stage P to smem ----
#pragma unroll
        for (int i = 0; i < 4; i++)
            *(float4*)&pS[r0 + i][c0] = make_float4(s[i][0], s[i][1], s[i][2], s[i][3]);
        __syncthreads();

        // ---- O += P @ h^T  (K=64) ----
#pragma unroll 4
        for (int n = 0; n < NT; n += 4) {
            float4 hq0 = *(const float4*)&hS[c0 + 0][n];
            float4 hq1 = *(const float4*)&hS[c0 + 1][n];
            float4 hq2 = *(const float4*)&hS[c0 + 2][n];
            float4 hq3 = *(const float4*)&hS[c0 + 3][n];
#pragma unroll
            for (int i = 0; i < 4; i++) {
                float4 pq = *(const float4*)&pS[r0 + i][n];
                acc[i][0] = fmaf(pq.x, hq0.x, acc[i][0]);
                acc[i][0] = fmaf(pq.y, hq0.y, acc[i][0]);
                acc[i][0] = fmaf(pq.z, hq0.z, acc[i][0]);
                acc[i][0] = fmaf(pq.w, hq0.w, acc[i][0]);
                acc[i][1] = fmaf(pq.x, hq1.x, acc[i][1]);
                acc[i][1] = fmaf(pq.y, hq1.y, acc[i][1]);
                acc[i][1] = fmaf(pq.z, hq1.z, acc[i][1]);
                acc[i][1] = fmaf(pq.w, hq1.w, acc[i][1]);
                acc[i][2] = fmaf(pq.x, hq2.x, acc[i][2]);
                acc[i][2] = fmaf(pq.y, hq2.y, acc[i][2]);
                acc[i][2] = fmaf(pq.z, hq2.z, acc[i][2]);
                acc[i][2] = fmaf(pq.w, hq2.w, acc[i][2]);
                acc[i][3] = fmaf(pq.x, hq3.x, acc[i][3]);
                acc[i][3] = fmaf(pq.y, hq3.y, acc[i][3]);
                acc[i][3] = fmaf(pq.z, hq3.z, acc[i][3]);
                acc[i][3] = fmaf(pq.w, hq3.w, acc[i][3]);
            }
        }
        __syncthreads();
    }

    // ---- epilogue: out[b, c, m] = gamma * acc[m][c]/li[m] + x[b, c, m] ----
    const float gm = *gamma_p;
    float inv[4];
#pragma unroll
    for (int i = 0; i < 4; i++) inv[i] = 1.0f / li[i];

#pragma unroll
    for (int j = 0; j < 4; j++) {
        const int c = c0 + j;  // channel (0..63)
        const size_t base = (size_t)b * C_ * N_ + (size_t)c * N_ + m0 + r0;
        float4 xv = *(const float4*)&x[base];
        float4 ov;
        ov.x = fmaf(gm, acc[0][j] * inv[0], xv.x);
        ov.y = fmaf(gm, acc[1][j] * inv[1], xv.y);
        ov.z = fmaf(gm, acc[2][j] * inv[2], xv.z);
        ov.w = fmaf(gm, acc[3][j] * inv[3], xv.w);
        *(float4*)&out[base] = ov;
    }
}

// ---------------------------------------------------------------------------
extern "C" void kernel_launch(void* const* d_in, const int* in_sizes, int n_in,
                              void* d_out, int out_size)
{
    const float* x     = (const float*)d_in[0];
    const float* y     = (const float*)d_in[1];
    const float* Wf    = (const float*)d_in[2];
    const float* bf    = (const float*)d_in[3];
    const float* Wg    = (const float*)d_in[4];
    const float* bg    = (const float*)d_in[5];
    const float* Wh    = (const float*)d_in[6];
    const float* bh    = (const float*)d_in[7];
    const float* gamma = (const float*)d_in[8];
    float* out = (float*)d_out;

    float *fp, *gp, *hp;
    cudaGetSymbolAddress((void**)&fp, g_fbuf);
    cudaGetSymbolAddress((void**)&gp, g_gbuf);
    cudaGetSymbolAddress((void**)&hp, g_hbuf);

    dim3 pb(256);
    proj_kernel<<<dim3(B_ * N_ / 256, CK / 16), pb>>>(Wf, bf, x, fp, CK);
    proj_kernel<<<dim3(B_ * N_ / 256, CK / 16), pb>>>(Wg, bg, y, gp, CK);
    proj_kernel<<<dim3(B_ * N_ / 256, C_ / 16), pb>>>(Wh, bh, y, hp, C_);

    attn_kernel<<<dim3(N_ / MT, B_), 256>>>(x, gamma, out);
}

// round 17
// speedup vs baseline: 5.3173x; 5.3173x over previous
#include <cuda_runtime.h>
#include <cstdint>

#define B_  4
#define C_  64
#define N_  4096
#define CK  32       // f/g channel count
#define MT  128      // query rows per CTA
#define NT  64       // key tile width

// ---------------------------------------------------------------------------
// Scratch for projected tensors (tf32-rounded fp32)
// ---------------------------------------------------------------------------
__device__ float g_fbuf[B_ * CK * N_];
__device__ float g_gbuf[B_ * CK * N_];
__device__ float g_hbuf[B_ * C_ * N_];

__device__ __forceinline__ float tf32r(float v) {
    float o; asm("cvt.rna.tf32.f32 %0, %1;" : "=f"(o) : "f"(v)); return o;
}

// m16n8k8 tf32 MMA (plain PTX — works on family target sm_103)
__device__ __forceinline__ void mma8(float* c, const uint32_t* a, const uint32_t* b) {
    asm volatile(
        "mma.sync.aligned.m16n8k8.row.col.f32.tf32.tf32.f32 "
        "{%0,%1,%2,%3}, {%4,%5,%6,%7}, {%8,%9}, {%0,%1,%2,%3};"
        : "+f"(c[0]), "+f"(c[1]), "+f"(c[2]), "+f"(c[3])
        : "r"(a[0]), "r"(a[1]), "r"(a[2]), "r"(a[3]), "r"(b[0]), "r"(b[1]));
}

// ---------------------------------------------------------------------------
// Projection: out[b, oc, n] = sum_c W[oc, c] * in[b, c, n] + bias[oc], tf32-rounded
// ---------------------------------------------------------------------------
__global__ __launch_bounds__(256) void proj_kernel(
    const float* __restrict__ W, const float* __restrict__ bias,
    const float* __restrict__ in, float* __restrict__ out, int OC)
{
    __shared__ float Ws[16][64];
    const int oc0 = blockIdx.y * 16;
    const int t = threadIdx.x;
    for (int i = t; i < 16 * 64; i += 256)
        Ws[i >> 6][i & 63] = W[(oc0 + (i >> 6)) * C_ + (i & 63)];
    __syncthreads();

    const int pix = blockIdx.x * 256 + t;
    const int b = pix >> 12;
    const int n = pix & (N_ - 1);
    const float* inp = in + (size_t)b * C_ * N_ + n;

    float acc[16];
#pragma unroll
    for (int o = 0; o < 16; o++) acc[o] = bias[oc0 + o];
#pragma unroll 4
    for (int c = 0; c < C_; c++) {
        float v = inp[(size_t)c * N_];
#pragma unroll
        for (int o = 0; o < 16; o++) acc[o] = fmaf(Ws[o][c], v, acc[o]);
    }
    float* op = out + (size_t)b * OC * N_ + (size_t)oc0 * N_ + n;
#pragma unroll
    for (int o = 0; o < 16; o++) op[(size_t)o * N_] = tf32r(acc[o]);
}

// ---------------------------------------------------------------------------
// mma.sync tf32 flash attention, no-max softmax, O resident in registers.
//   8 warps: warp_m = wid>>1 (32 rows each), warp_n = wid&1 (32 cols each)
// SMEM (floats):
//   gT [128][36]   A of GEMM1: gT[m][c]        (A-load bank = 4g+q: conflict-free)
//   fS [32][72]    B of GEMM1: fS[c][n]        (B-load bank = 8q+g: conflict-free)
//   hS [64][68]    B of GEMM2: hS[c][n]        (B-load bank = 4g+q: conflict-free)
//   P  [128][68]   A of GEMM2: P[m][n]         (A-load bank = 4g+q: conflict-free)
//   li [128]
// ---------------------------------------------------------------------------
#define GT_S 36
#define FS_S 72
#define HS_S 68
#define P_S  68
#define OFF_GT 0
#define OFF_FS (OFF_GT + MT * GT_S)            // 4608
#define OFF_HS (OFF_FS + CK * FS_S)            // 6912
#define OFF_P  (OFF_HS + C_ * HS_S)            // 11264
#define OFF_LI (OFF_P + MT * P_S)              // 19968
#define SMEM_FLOATS (OFF_LI + MT)              // 20096
#define SMEM_BYTES (SMEM_FLOATS * 4)           // 80384

__global__ __launch_bounds__(256, 2) void attn_mma(
    const float* __restrict__ x, const float* __restrict__ gamma_p,
    float* __restrict__ out)
{
    extern __shared__ float s[];
    float* gT = s + OFF_GT;
    float* fS = s + OFF_FS;
    float* hS = s + OFF_HS;
    float* P  = s + OFF_P;
    float* li = s + OFF_LI;

    const int t = threadIdx.x;
    const int wid = t >> 5, lane = t & 31;
    const int g = lane >> 2, q = lane & 3;
    const int warp_m = wid >> 1, warp_n = wid & 1;
    const int R = warp_m * 32;        // row base of this warp
    const int Cb = warp_n * 32;       // col base of this warp
    const int b = blockIdx.y;
    const int m0 = blockIdx.x * MT;

    const float* fb = g_fbuf + (size_t)b * CK * N_;
    const float* gb = g_gbuf + (size_t)b * CK * N_;
    const float* hb = g_hbuf + (size_t)b * C_ * N_;

    if (t < MT) li[t] = 0.f;

    // ---- load g tile once: gT[m][c] ----
    for (int v = t; v < (MT * CK) / 4; v += 256) {   // 1024 float4 reads along m
        int k = v >> 5, mq = (v & 31) * 4;
        float4 qv = *(const float4*)&gb[(size_t)k * N_ + m0 + mq];
        gT[(mq + 0) * GT_S + k] = qv.x;
        gT[(mq + 1) * GT_S + k] = qv.y;
        gT[(mq + 2) * GT_S + k] = qv.z;
        gT[(mq + 3) * GT_S + k] = qv.w;
    }

    float oc[2][4][4];                 // O accumulators: rows R+16mt+g(+8), cols Cb+8nt+2q(+1)
#pragma unroll
    for (int mt = 0; mt < 2; mt++)
#pragma unroll
        for (int nt = 0; nt < 4; nt++)
#pragma unroll
            for (int r = 0; r < 4; r++) oc[mt][nt][r] = 0.f;
    float lsum[4] = {0.f, 0.f, 0.f, 0.f};   // row partials: R+g, R+8+g, R+16+g, R+24+g

    for (int n0 = 0; n0 < N_; n0 += NT) {
        // ---- load f tile fS[c][n], h tile hS[c][n] (coalesced float4) ----
        for (int v = t; v < (CK * NT) / 4; v += 256) {    // 512
            int c = v >> 4, nq = (v & 15) * 4;
            *(float4*)&fS[c * FS_S + nq] = *(const float4*)&fb[(size_t)c * N_ + n0 + nq];
        }
        for (int v = t; v < (C_ * NT) / 4; v += 256) {    // 1024
            int c = v >> 4, nq = (v & 15) * 4;
            *(float4*)&hS[c * HS_S + nq] = *(const float4*)&hb[(size_t)c * N_ + n0 + nq];
        }
        __syncthreads();

        // ---- GEMM1: S[128x64] = gT . fS, K=32 ----
        float sc[2][4][4];
#pragma unroll
        for (int mt = 0; mt < 2; mt++)
#pragma unroll
            for (int nt = 0; nt < 4; nt++)
#pragma unroll
                for (int r = 0; r < 4; r++) sc[mt][nt][r] = 0.f;

#pragma unroll
        for (int kk = 0; kk < 4; kk++) {
            const int k0 = kk * 8;
            uint32_t A[2][4];
#pragma unroll
            for (int mt = 0; mt < 2; mt++) {
                const float* ap = &gT[(R + 16 * mt + g) * GT_S + k0 + q];
                A[mt][0] = __float_as_uint(ap[0]);
                A[mt][1] = __float_as_uint(ap[8 * GT_S]);
                A[mt][2] = __float_as_uint(ap[4]);
                A[mt][3] = __float_as_uint(ap[8 * GT_S + 4]);
            }
#pragma unroll
            for (int nt = 0; nt < 4; nt++) {
                uint32_t Bv[2];
                Bv[0] = __float_as_uint(fS[(k0 + q) * FS_S + Cb + 8 * nt + g]);
                Bv[1] = __float_as_uint(fS[(k0 + q + 4) * FS_S + Cb + 8 * nt + g]);
#pragma unroll
                for (int mt = 0; mt < 2; mt++) mma8(sc[mt][nt], A[mt], Bv);
            }
        }

        // ---- exp (no max-sub), row-sum partials, stage P (tf32) ----
#pragma unroll
        for (int mt = 0; mt < 2; mt++) {
#pragma unroll
            for (int nt = 0; nt < 4; nt++) {
                float p0 = __expf(sc[mt][nt][0]);
                float p1 = __expf(sc[mt][nt][1]);
                float p2 = __expf(sc[mt][nt][2]);
                float p3 = __expf(sc[mt][nt][3]);
                lsum[2 * mt + 0] += p0 + p1;
                lsum[2 * mt + 1] += p2 + p3;
                float* pp = &P[(R + 16 * mt + g) * P_S + Cb + 8 * nt + 2 * q];
                *(float2*)pp = make_float2(tf32r(p0), tf32r(p1));
                *(float2*)(pp + 8 * P_S) = make_float2(tf32r(p2), tf32r(p3));
            }
        }
        __syncthreads();   // P complete (cross-warp) before GEMM2 reads it

        // ---- GEMM2: O[128x64] += P . hS^T, K=64 ----
#pragma unroll
        for (int kk = 0; kk < 8; kk++) {
            const int k0 = kk * 8;
            uint32_t A[2][4];
#pragma unroll
            for (int mt = 0; mt < 2; mt++) {
                const float* ap = &P[(R + 16 * mt + g) * P_S + k0 + q];
                A[mt][0] = __float_as_uint(ap[0]);
                A[mt][1] = __float_as_uint(ap[8 * P_S]);
                A[mt][2] = __float_as_uint(ap[4]);
                A[mt][3] = __float_as_uint(ap[8 * P_S + 4]);
            }
#pragma unroll
            for (int nt = 0; nt < 4; nt++) {
                uint32_t Bv[2];
                Bv[0] = __float_as_uint(hS[(Cb + 8 * nt + g) * HS_S + k0 + q]);
                Bv[1] = __float_as_uint(hS[(Cb + 8 * nt + g) * HS_S + k0 + q + 4]);
#pragma unroll
                for (int mt = 0; mt < 2; mt++) mma8(oc[mt][nt], A[mt], Bv);
            }
        }
        __syncthreads();   // done with fS/hS/P before next tile overwrites
    }

    // ---- finalize row sums: quad reduce then combine across warp_n ----
#pragma unroll
    for (int i = 0; i < 4; i++) {
        float v = lsum[i];
        v += __shfl_xor_sync(0xffffffffu, v, 1);
        v += __shfl_xor_sync(0xffffffffu, v, 2);
        if (q == 0) atomicAdd(&li[R + 16 * (i >> 1) + 8 * (i & 1) + g], v);
    }
    __syncthreads();

    // ---- epilogue: out[b,c,m] = gamma * O[m][c]/li[m] + x[b,c,m] ----
    const float gm = *gamma_p;
    float inv0[2], inv1[2];
#pragma unroll
    for (int mt = 0; mt < 2; mt++) {
        inv0[mt] = 1.0f / li[R + 16 * mt + g];
        inv1[mt] = 1.0f / li[R + 16 * mt + 8 + g];
    }
    const size_t xbase = (size_t)b * C_ * N_ + m0;
#pragma unroll
    for (int mt = 0; mt < 2; mt++) {
        const int r1 = R + 16 * mt + g;
#pragma unroll
        for (int nt = 0; nt < 4; nt++) {
            const int cc = Cb + 8 * nt + 2 * q;
            const size_t i00 = xbase + (size_t)cc * N_ + r1;
            const size_t i01 = xbase + (size_t)(cc + 1) * N_ + r1;
            out[i00]     = fmaf(gm, oc[mt][nt][0] * inv0[mt], x[i00]);
            out[i01]     = fmaf(gm, oc[mt][nt][1] * inv0[mt], x[i01]);
            out[i00 + 8] = fmaf(gm, oc[mt][nt][2] * inv1[mt], x[i00 + 8]);
            out[i01 + 8] = fmaf(gm, oc[mt][nt][3] * inv1[mt], x[i01 + 8]);
        }
    }
}

// ---------------------------------------------------------------------------
extern "C" void kernel_launch(void* const* d_in, const int* in_sizes, int n_in,
                              void* d_out, int out_size)
{
    const float* x     = (const float*)d_in[0];
    const float* y     = (const float*)d_in[1];
    const float* Wf    = (const float*)d_in[2];
    const float* bf    = (const float*)d_in[3];
    const float* Wg    = (const float*)d_in[4];
    const float* bg    = (const float*)d_in[5];
    const float* Wh    = (const float*)d_in[6];
    const float* bh    = (const float*)d_in[7];
    const float* gamma = (const float*)d_in[8];
    float* out = (float*)d_out;

    float *fp, *gp, *hp;
    cudaGetSymbolAddress((void**)&fp, g_fbuf);
    cudaGetSymbolAddress((void**)&gp, g_gbuf);
    cudaGetSymbolAddress((void**)&hp, g_hbuf);

    cudaFuncSetAttribute(attn_mma, cudaFuncAttributeMaxDynamicSharedMemorySize, SMEM_BYTES);

    dim3 pb(256);
    proj_kernel<<<dim3(B_ * N_ / 256, CK / 16), pb>>>(Wf, bf, x, fp, CK);
    proj_kernel<<<dim3(B_ * N_ / 256, CK / 16), pb>>>(Wg, bg, y, gp, CK);
    proj_kernel<<<dim3(B_ * N_ / 256, C_ / 16), pb>>>(Wh, bh, y, hp, C_);

    attn_mma<<<dim3(N_ / MT, B_), 256, SMEM_BYTES>>>(x, gamma, out);
}